// round 4
// baseline (speedup 1.0000x reference)
#include <cuda_runtime.h>
#include <math.h>

#define NNODE 50000
#define EMB 35
#define DEG 32
#define NBSTRIDE 40   // padded row: 160B, 32B aligned; element 35 holds s_b

typedef unsigned long long ull;

// ---------------- scratch (device globals; no runtime allocation) ----------------
__device__ float g_nb[4][NNODE * NBSTRIDE];  // transformed neighbor rows (+ s_b at [35])
__device__ float g_sa[4][NNODE];             // per-node src-side attention score
__device__ float g_m [4][NNODE * EMB];       // aggregation results

// ---------------- packed f32x2 helpers ----------------
static __device__ __forceinline__ ull pack2(float a, float b) {
    ull r;
    unsigned int lo = __float_as_uint(a), hi = __float_as_uint(b);
    asm("mov.b64 %0, {%1, %2};" : "=l"(r) : "r"(lo), "r"(hi));
    return r;
}
static __device__ __forceinline__ void unpack2(ull v, float &a, float &b) {
    unsigned int lo, hi;
    asm("mov.b64 {%0, %1}, %2;" : "=r"(lo), "=r"(hi) : "l"(v));
    a = __uint_as_float(lo);
    b = __uint_as_float(hi);
}
#define FMA2(d, a, b, c) \
    asm("fma.rn.f32x2 %0, %1, %2, %3;" : "=l"(d) : "l"(a), "l"(b), "l"(c))

// ---------------- kernel args ----------------
struct TArgs {
    const float* fsrc[4];
    const float* fdst[4];
    const float* W[4];
    const float* b[4];
    const float* att[4];
};
struct AArgs {
    const int* dst[4];
};

// =====================================================================
// Kernel 1: nb = fsrc @ W + b ; row[35] = nb @ att[35:70] ; s_a = fdst @ att[0:35]
// Features staged via smem (coalesced gmem, conflict-free stride-37 LDS).
// =====================================================================
__global__ __launch_bounds__(128) void transform_kernel(TArgs args) {
    const int jid = blockIdx.y;
    const float* __restrict__ W   = args.W[jid];
    const float* __restrict__ bv  = args.b[jid];
    const float* __restrict__ att = args.att[jid];

    __shared__ __align__(16) float Xs[128 * 37];   // staged feature rows
    __shared__ __align__(16) float Wsh[EMB * 36];
    __shared__ __align__(16) ull bp[18];
    __shared__ __align__(16) ull ahp[18];
    __shared__ __align__(16) float alo[EMB];

    const int tid = threadIdx.x;
    for (int i = tid; i < EMB * 36; i += 128) {
        int k = i / 36, c = i % 36;
        Wsh[i] = (c < EMB) ? W[k * EMB + c] : 0.0f;
    }
    if (tid < 18) {
        int c = 2 * tid;
        bp[tid]  = pack2(bv[c],        (c + 1 < EMB) ? bv[c + 1]        : 0.0f);
        ahp[tid] = pack2(att[EMB + c], (c + 1 < EMB) ? att[EMB + c + 1] : 0.0f);
    }
    if (tid < EMB) alo[tid] = att[tid];

    const int base  = blockIdx.x * 128;
    const int nrows = min(128, NNODE - base);
    const int total = nrows * EMB;

    // ---- stage fdst rows, compute s_a ----
    {
        const float* __restrict__ src = args.fdst[jid] + base * EMB;
        for (int g = tid; g < total; g += 128)
            Xs[(g / EMB) * 37 + (g % EMB)] = src[g];
    }
    __syncthreads();
    if (tid < nrows) {
        const float* xr = Xs + tid * 37;
        float sa = 0.0f;
#pragma unroll
        for (int k = 0; k < EMB; k++) sa = fmaf(xr[k], alo[k], sa);
        g_sa[jid][base + tid] = sa;
    }
    __syncthreads();

    // ---- stage fsrc rows, compute nb row + s_b ----
    {
        const float* __restrict__ src = args.fsrc[jid] + base * EMB;
        for (int g = tid; g < total; g += 128)
            Xs[(g / EMB) * 37 + (g % EMB)] = src[g];
    }
    __syncthreads();
    if (tid >= nrows) return;

    ull acc[18];
#pragma unroll
    for (int i = 0; i < 18; i++) acc[i] = bp[i];

    const float* xr = Xs + tid * 37;
#pragma unroll 5
    for (int k = 0; k < EMB; k++) {
        float xv = xr[k];
        ull xx = pack2(xv, xv);
        const ulonglong2* wr = reinterpret_cast<const ulonglong2*>(Wsh + k * 36);
#pragma unroll
        for (int i = 0; i < 9; i++) {
            ulonglong2 wv = wr[i];
            FMA2(acc[2 * i],     wv.x, xx, acc[2 * i]);
            FMA2(acc[2 * i + 1], wv.y, xx, acc[2 * i + 1]);
        }
    }

    // s_b = nb . att_hi (pad lanes zero on both sides)
    ull sp = 0ull;
#pragma unroll
    for (int i = 0; i < 18; i++) FMA2(sp, acc[i], ahp[i], sp);
    float s0, s1;
    unpack2(sp, s0, s1);

    // fold s_b into row slot 35 (hi half of acc[17])
    float c34, padv;
    unpack2(acc[17], c34, padv);
    acc[17] = pack2(c34, s0 + s1);

    ull* outr = reinterpret_cast<ull*>(&g_nb[jid][(base + tid) * NBSTRIDE]);
#pragma unroll
    for (int i = 0; i < 18; i++) outr[i] = acc[i];
}

// =====================================================================
// Kernel 2: attention aggregation. One warp per node (DEG==32 lanes).
// s_b read from the row itself (primes L1/L2 for phase 2).
// =====================================================================
__global__ __launch_bounds__(256) void agg_kernel(AArgs args) {
    const int jid = blockIdx.y;
    const float* __restrict__ nb  = g_nb[jid];
    const float* __restrict__ sav = g_sa[jid];
    const int*   __restrict__ dst = args.dst[jid];
    float* __restrict__ m = g_m[jid];

    __shared__ float sw[8][32];
    __shared__ int   soff[8][32];

    const int wid  = threadIdx.x >> 5;
    const int lane = threadIdx.x & 31;
    const int node = blockIdx.x * 8 + wid;
    if (node >= NNODE) return;

    const int d   = dst[node * DEG + lane];
    const int off = d * NBSTRIDE;
    float sb = nb[off + 35];
    float x  = sav[node] + sb;
    float e  = (x > 0.0f) ? x : 0.1f * expm1f(x);   // elu(alpha=0.1)
    float w  = expf(e);

    float wsum = w;
#pragma unroll
    for (int o = 16; o; o >>= 1) wsum += __shfl_xor_sync(0xffffffffu, wsum, o);

    sw[wid][lane]   = w;
    soff[wid][lane] = off;
    __syncwarp();

    if (lane < 18) {
        float ax = 0.0f, ay = 0.0f;
        const float* bp2 = nb + 2 * lane;
#pragma unroll
        for (int j = 0; j < 32; j++) {
            float wj = sw[wid][j];
            float2 v = *reinterpret_cast<const float2*>(bp2 + soff[wid][j]);
            ax = fmaf(wj, v.x, ax);
            ay = fmaf(wj, v.y, ay);
        }
        float inv = 1.0f / wsum;
        int c = 2 * lane;
        float* mr = m + node * EMB;
        mr[c] = ax * inv;
        if (c + 1 < EMB) mr[c + 1] = ay * inv;
    }
}

// =====================================================================
// Kernel 3 (merged a+b): out = prelu([feat, m_pos, m_neg] @ W1 + b1) @ W2 + b2
// 4 threads per node. Roles exchange PReLU'd h through smem (same warp ->
// __syncwarp only), then each role sums its own 4-5 output pairs over all
// 70 k values. No shuffles, no redundant GEMM2 work.
// 512 threads = 128 nodes per block.
// =====================================================================
__global__ __launch_bounds__(512) void update_kernel(
    const float* __restrict__ fa, const float* __restrict__ fb,
    const float* __restrict__ W1, const float* __restrict__ b1,
    const float* __restrict__ alpha_p,
    const float* __restrict__ W2, const float* __restrict__ b2,
    float* __restrict__ out)
{
    __shared__ __align__(16) float W1sh[105 * 72];   // 30240B, rows padded 70->72
    __shared__ __align__(16) ull   w2p[70 * 18];     // 10080B, packed col pairs (35->36)
    __shared__ __align__(16) float hs[128 * 73];     // 37376B, h exchange (stride 73: conflict-free)
    __shared__ __align__(16) ull b1p[36];
    __shared__ __align__(16) ull b2p[18];

    const int tid = threadIdx.x;
    for (int i = tid; i < 105 * 72; i += 512) {
        int k = i / 72, c = i % 72;
        W1sh[i] = (c < 70) ? W1[k * 70 + c] : 0.0f;
    }
    for (int i = tid; i < 70 * 18; i += 512) {
        int k = i / 18, j = i % 18;
        int c = 2 * j;
        w2p[i] = pack2(W2[k * EMB + c], (c + 1 < EMB) ? W2[k * EMB + c + 1] : 0.0f);
    }
    if (tid < 36) {
        int c = 2 * tid;
        b1p[tid] = pack2(b1[c], (c + 1 < 70) ? b1[c + 1] : 0.0f);
    }
    if (tid < 18) {
        int c = 2 * tid;
        b2p[tid] = pack2(b2[c], (c + 1 < EMB) ? b2[c + 1] : 0.0f);
    }
    __syncthreads();

    const int node_l = tid >> 2;
    const int role   = tid & 3;
    const int node   = blockIdx.x * 128 + node_l;          // 0 .. 2*NNODE-1
    const bool valid = (node < 2 * NNODE);
    const int  nc    = valid ? node : (2 * NNODE - 1);

    const float* xr;
    const float* m0;
    const float* m1;
    if (nc < NNODE) {
        xr = fa + nc * EMB;
        m0 = g_m[0] + nc * EMB;
        m1 = g_m[1] + nc * EMB;
    } else {
        int nl = nc - NNODE;
        xr = fb + nl * EMB;
        m0 = g_m[2] + nl * EMB;
        m1 = g_m[3] + nl * EMB;
    }
    const float alpha = __ldg(alpha_p);

    // ---- GEMM1: this role computes h pairs [9*role, 9*role+9) ----
    ull acc[9];
#pragma unroll
    for (int i = 0; i < 9; i++) acc[i] = b1p[9 * role + i];

    const float* srcs[3] = { xr, m0, m1 };
    const ull* w1base = reinterpret_cast<const ull*>(W1sh) + 9 * role;
#pragma unroll
    for (int part = 0; part < 3; part++) {
        const float* x = srcs[part];
        const ull* wb = w1base + (part * EMB) * 36;
#pragma unroll 5
        for (int k = 0; k < EMB; k++) {
            float xv = x[k];
            ull xx = pack2(xv, xv);
            const ull* wr = wb + k * 36;
#pragma unroll
            for (int i = 0; i < 9; i++) FMA2(acc[i], wr[i], xx, acc[i]);
        }
    }

    // ---- PReLU, publish h to smem (quad lives in one warp) ----
    float* hrow = hs + node_l * 73;
#pragma unroll
    for (int i = 0; i < 9; i++) {
        float h0, h1;
        unpack2(acc[i], h0, h1);
        h0 = (h0 > 0.0f) ? h0 : alpha * h0;
        h1 = (h1 > 0.0f) ? h1 : alpha * h1;
        int c = 18 * role + 2 * i;
        hrow[c]     = h0;
        hrow[c + 1] = h1;
    }
    __syncwarp();

    // ---- GEMM2: role owns output pairs [p0, p0+np) ----
    const int p0 = (role < 2) ? role * 5 : 10 + (role - 2) * 4;
    const int np = (role < 2) ? 5 : 4;

    ull acc2[5];
#pragma unroll
    for (int q = 0; q < 5; q++) acc2[q] = (q < np) ? b2p[p0 + q] : 0ull;

#pragma unroll 2
    for (int k = 0; k < 70; k++) {
        float hv = hrow[k];
        ull xx = pack2(hv, hv);
        const ull* wr = w2p + k * 18 + p0;
#pragma unroll
        for (int q = 0; q < 5; q++)
            if (q < np) FMA2(acc2[q], wr[q], xx, acc2[q]);
    }

    if (valid) {
        float* orow = out + node * EMB;
#pragma unroll
        for (int q = 0; q < 5; q++) {
            if (q < np) {
                float v0, v1;
                unpack2(acc2[q], v0, v1);
                int c = 2 * (p0 + q);
                orow[c] = v0;
                if (c + 1 < EMB) orow[c + 1] = v1;
            }
        }
    }
}

// =====================================================================
// launch
// =====================================================================
extern "C" void kernel_launch(void* const* d_in, const int* in_sizes, int n_in,
                              void* d_out, int out_size) {
    const float* fa = (const float*)d_in[0];
    const float* fb = (const float*)d_in[1];

    TArgs t;
    const float* fsrc[4] = { fb, fb, fa, fa };
    const float* fdst[4] = { fa, fa, fb, fb };
    for (int j = 0; j < 4; j++) {
        t.fsrc[j] = fsrc[j];
        t.fdst[j] = fdst[j];
        t.W[j]   = (const float*)d_in[6 + 3 * j];
        t.b[j]   = (const float*)d_in[7 + 3 * j];
        t.att[j] = (const float*)d_in[8 + 3 * j];
    }
    AArgs a;
    a.dst[0] = (const int*)d_in[2];
    a.dst[1] = (const int*)d_in[3];
    a.dst[2] = (const int*)d_in[4];
    a.dst[3] = (const int*)d_in[5];

    const float* W1 = (const float*)d_in[18];
    const float* b1 = (const float*)d_in[19];
    const float* al = (const float*)d_in[20];
    const float* W2 = (const float*)d_in[21];
    const float* b2 = (const float*)d_in[22];
    float* out = (float*)d_out;

    dim3 tg((NNODE + 127) / 128, 4);
    transform_kernel<<<tg, 128>>>(t);

    dim3 ag((NNODE + 7) / 8, 4);
    agg_kernel<<<ag, 256>>>(a);

    dim3 ug((2 * NNODE + 127) / 128);
    update_kernel<<<ug, 512>>>(fa, fb, W1, b1, al, W2, b2, out);
}

// round 5
// speedup vs baseline: 1.1224x; 1.1224x over previous
#include <cuda_runtime.h>
#include <cuda_fp16.h>
#include <math.h>

#define NNODE 50000
#define EMB 35
#define DEG 32
#define NBH 36          // halves per nb row (35 ch + 1 zero pad) = 72B

typedef unsigned long long ull;

// ---------------- scratch (device globals; no runtime allocation) ----------------
__device__ __half g_nbh[4][NNODE * NBH];   // transformed neighbor rows, fp16, 72B/row
__device__ float  g_sb[4][NNODE];          // dst-side attention score (fp32, compact)
__device__ float  g_sa[4][NNODE];          // src-side attention score
__device__ float  g_m [4][NNODE * EMB];    // aggregation results

// ---------------- packed f32x2 helpers ----------------
static __device__ __forceinline__ ull pack2(float a, float b) {
    ull r;
    unsigned int lo = __float_as_uint(a), hi = __float_as_uint(b);
    asm("mov.b64 %0, {%1, %2};" : "=l"(r) : "r"(lo), "r"(hi));
    return r;
}
static __device__ __forceinline__ void unpack2(ull v, float &a, float &b) {
    unsigned int lo, hi;
    asm("mov.b64 {%0, %1}, %2;" : "=r"(lo), "=r"(hi) : "l"(v));
    a = __uint_as_float(lo);
    b = __uint_as_float(hi);
}
#define FMA2(d, a, b, c) \
    asm("fma.rn.f32x2 %0, %1, %2, %3;" : "=l"(d) : "l"(a), "l"(b), "l"(c))

// ---------------- kernel args ----------------
struct TArgs {
    const float* fsrc[4];
    const float* fdst[4];
    const float* W[4];
    const float* b[4];
    const float* att[4];
};
struct AArgs {
    const int* dst[4];
};

// =====================================================================
// Kernel 1: job-pair fused transform.
// pair 0 = jobs {0,1} (fsrc=fb), pair 1 = jobs {2,3} (fsrc=fa).
// One feature-row load feeds BOTH weight matrices (2x FMA per byte).
// nb rows written fp16 (36 halves = 72B); s_a/s_b fp32 to compact tables.
// =====================================================================
__global__ __launch_bounds__(128) void transform_kernel(TArgs args) {
    const int pair = blockIdx.y;          // 0 or 1
    const int j0 = 2 * pair, j1 = j0 + 1;

    __shared__ __align__(16) float Wsh[2][EMB * 36];
    __shared__ __align__(16) ull bp[2][18];
    __shared__ __align__(16) ull ahp[2][18];
    __shared__ __align__(16) float alo[2][EMB];

    const int tid = threadIdx.x;
#pragma unroll
    for (int jj = 0; jj < 2; jj++) {
        const int jid = j0 + jj;
        const float* __restrict__ W   = args.W[jid];
        const float* __restrict__ bv  = args.b[jid];
        const float* __restrict__ att = args.att[jid];
        for (int i = tid; i < EMB * 36; i += 128) {
            int k = i / 36, c = i % 36;
            Wsh[jj][i] = (c < EMB) ? W[k * EMB + c] : 0.0f;
        }
        if (tid < 18) {
            int c = 2 * tid;
            bp[jj][tid]  = pack2(bv[c],        (c + 1 < EMB) ? bv[c + 1]        : 0.0f);
            ahp[jj][tid] = pack2(att[EMB + c], (c + 1 < EMB) ? att[EMB + c + 1] : 0.0f);
        }
        if (tid < EMB) alo[jj][tid] = att[tid];
    }
    __syncthreads();

    const int row = blockIdx.x * 128 + tid;
    if (row >= NNODE) return;

    // ---- both transforms over one fsrc row ----
    ull a0[18], a1[18];
#pragma unroll
    for (int i = 0; i < 18; i++) { a0[i] = bp[0][i]; a1[i] = bp[1][i]; }

    const float* xr = args.fsrc[j0] + row * EMB;
#pragma unroll 5
    for (int k = 0; k < EMB; k++) {
        float xv = __ldg(xr + k);
        ull xx = pack2(xv, xv);
        const ulonglong2* w0 = reinterpret_cast<const ulonglong2*>(Wsh[0] + k * 36);
        const ulonglong2* w1 = reinterpret_cast<const ulonglong2*>(Wsh[1] + k * 36);
#pragma unroll
        for (int i = 0; i < 9; i++) {
            ulonglong2 v0 = w0[i];
            ulonglong2 v1 = w1[i];
            FMA2(a0[2 * i],     v0.x, xx, a0[2 * i]);
            FMA2(a0[2 * i + 1], v0.y, xx, a0[2 * i + 1]);
            FMA2(a1[2 * i],     v1.x, xx, a1[2 * i]);
            FMA2(a1[2 * i + 1], v1.y, xx, a1[2 * i + 1]);
        }
    }

    // ---- s_b per job (fp32, from unquantized acc) ----
    {
        ull sp0 = 0ull, sp1 = 0ull;
#pragma unroll
        for (int i = 0; i < 18; i++) {
            FMA2(sp0, a0[i], ahp[0][i], sp0);
            FMA2(sp1, a1[i], ahp[1][i], sp1);
        }
        float x0, y0, x1, y1;
        unpack2(sp0, x0, y0);
        unpack2(sp1, x1, y1);
        g_sb[j0][row] = x0 + y0;
        g_sb[j1][row] = x1 + y1;
    }

    // ---- store fp16 rows (9 x 8B per job; pad channel 35 is already 0) ----
    {
        ull* r0 = reinterpret_cast<ull*>(&g_nbh[j0][row * NBH]);
        ull* r1 = reinterpret_cast<ull*>(&g_nbh[j1][row * NBH]);
#pragma unroll
        for (int i = 0; i < 9; i++) {
            float f0, f1, f2, f3;
            unpack2(a0[2 * i], f0, f1);
            unpack2(a0[2 * i + 1], f2, f3);
            __half2 hA = __floats2half2_rn(f0, f1);
            __half2 hB = __floats2half2_rn(f2, f3);
            r0[i] = pack2(__uint_as_float(*reinterpret_cast<unsigned int*>(&hA)),
                          __uint_as_float(*reinterpret_cast<unsigned int*>(&hB)));
            unpack2(a1[2 * i], f0, f1);
            unpack2(a1[2 * i + 1], f2, f3);
            hA = __floats2half2_rn(f0, f1);
            hB = __floats2half2_rn(f2, f3);
            r1[i] = pack2(__uint_as_float(*reinterpret_cast<unsigned int*>(&hA)),
                          __uint_as_float(*reinterpret_cast<unsigned int*>(&hB)));
        }
    }

    // ---- s_a for both jobs from one fdst row ----
    {
        const float* yr = args.fdst[j0] + row * EMB;
        float sa0 = 0.0f, sa1 = 0.0f;
#pragma unroll 7
        for (int k = 0; k < EMB; k++) {
            float yv = __ldg(yr + k);
            sa0 = fmaf(yv, alo[0][k], sa0);
            sa1 = fmaf(yv, alo[1][k], sa1);
        }
        g_sa[j0][row] = sa0;
        g_sa[j1][row] = sa1;
    }
}

// =====================================================================
// Kernel 2: attention aggregation. One warp per node (DEG==32 lanes).
// fp16 rows: each gathered row = 72B = exactly 3 sectors.
// =====================================================================
__global__ __launch_bounds__(256) void agg_kernel(AArgs args) {
    const int jid = blockIdx.y;
    const __half2* __restrict__ nbh =
        reinterpret_cast<const __half2*>(g_nbh[jid]);
    const float* __restrict__ sbv = g_sb[jid];
    const float* __restrict__ sav = g_sa[jid];
    const int*   __restrict__ dst = args.dst[jid];
    float* __restrict__ m = g_m[jid];

    __shared__ float sw[8][32];
    __shared__ int   soff[8][32];

    const int wid  = threadIdx.x >> 5;
    const int lane = threadIdx.x & 31;
    const int node = blockIdx.x * 8 + wid;
    if (node >= NNODE) return;

    const int d = dst[node * DEG + lane];
    float x = sav[node] + sbv[d];
    float e = (x > 0.0f) ? x : 0.1f * expm1f(x);   // elu(alpha=0.1)
    float w = expf(e);

    float wsum = w;
#pragma unroll
    for (int o = 16; o; o >>= 1) wsum += __shfl_xor_sync(0xffffffffu, wsum, o);

    sw[wid][lane]   = w;
    soff[wid][lane] = d * (NBH / 2);   // half2 index of row start
    __syncwarp();

    if (lane < 18) {
        float ax = 0.0f, ay = 0.0f;
#pragma unroll
        for (int j = 0; j < 32; j++) {
            float wj = sw[wid][j];
            float2 v = __half22float2(nbh[soff[wid][j] + lane]);
            ax = fmaf(wj, v.x, ax);
            ay = fmaf(wj, v.y, ay);
        }
        float inv = 1.0f / wsum;
        int c = 2 * lane;
        float* mr = m + node * EMB;
        mr[c] = ax * inv;
        if (c + 1 < EMB) mr[c + 1] = ay * inv;
    }
}

// =====================================================================
// Kernel 3 (merged a+b): out = prelu([feat, m_pos, m_neg] @ W1 + b1) @ W2 + b2
// 4 threads per node, h exchanged via smem (quad in one warp).
// 256 threads = 64 nodes per block; >= 3 blocks/SM guaranteed.
// =====================================================================
__global__ __launch_bounds__(256, 3) void update_kernel(
    const float* __restrict__ fa, const float* __restrict__ fb,
    const float* __restrict__ W1, const float* __restrict__ b1,
    const float* __restrict__ alpha_p,
    const float* __restrict__ W2, const float* __restrict__ b2,
    float* __restrict__ out)
{
    __shared__ __align__(16) float W1sh[105 * 72];   // 30240B
    __shared__ __align__(16) ull   w2p[70 * 18];     // 10080B
    __shared__ __align__(16) float hs[64 * 73];      // 18688B
    __shared__ __align__(16) ull b1p[36];
    __shared__ __align__(16) ull b2p[18];

    const int tid = threadIdx.x;
    for (int i = tid; i < 105 * 72; i += 256) {
        int k = i / 72, c = i % 72;
        W1sh[i] = (c < 70) ? W1[k * 70 + c] : 0.0f;
    }
    for (int i = tid; i < 70 * 18; i += 256) {
        int k = i / 18, j = i % 18;
        int c = 2 * j;
        w2p[i] = pack2(W2[k * EMB + c], (c + 1 < EMB) ? W2[k * EMB + c + 1] : 0.0f);
    }
    if (tid < 36) {
        int c = 2 * tid;
        b1p[tid] = pack2(b1[c], (c + 1 < 70) ? b1[c + 1] : 0.0f);
    }
    if (tid < 18) {
        int c = 2 * tid;
        b2p[tid] = pack2(b2[c], (c + 1 < EMB) ? b2[c + 1] : 0.0f);
    }
    __syncthreads();

    const int node_l = tid >> 2;
    const int role   = tid & 3;
    const int node   = blockIdx.x * 64 + node_l;           // 0 .. 2*NNODE-1
    const bool valid = (node < 2 * NNODE);
    const int  nc    = valid ? node : (2 * NNODE - 1);

    const float* xr;
    const float* m0;
    const float* m1;
    if (nc < NNODE) {
        xr = fa + nc * EMB;
        m0 = g_m[0] + nc * EMB;
        m1 = g_m[1] + nc * EMB;
    } else {
        int nl = nc - NNODE;
        xr = fb + nl * EMB;
        m0 = g_m[2] + nl * EMB;
        m1 = g_m[3] + nl * EMB;
    }
    const float alpha = __ldg(alpha_p);

    // ---- GEMM1: this role computes h pairs [9*role, 9*role+9) ----
    ull acc[9];
#pragma unroll
    for (int i = 0; i < 9; i++) acc[i] = b1p[9 * role + i];

    const float* srcs[3] = { xr, m0, m1 };
    const ull* w1base = reinterpret_cast<const ull*>(W1sh) + 9 * role;
#pragma unroll
    for (int part = 0; part < 3; part++) {
        const float* x = srcs[part];
        const ull* wb = w1base + (part * EMB) * 36;
#pragma unroll 5
        for (int k = 0; k < EMB; k++) {
            float xv = x[k];
            ull xx = pack2(xv, xv);
            const ull* wr = wb + k * 36;
#pragma unroll
            for (int i = 0; i < 9; i++) FMA2(acc[i], wr[i], xx, acc[i]);
        }
    }

    // ---- PReLU, publish h to smem (quad lives in one warp) ----
    float* hrow = hs + node_l * 73;
#pragma unroll
    for (int i = 0; i < 9; i++) {
        float h0, h1;
        unpack2(acc[i], h0, h1);
        h0 = (h0 > 0.0f) ? h0 : alpha * h0;
        h1 = (h1 > 0.0f) ? h1 : alpha * h1;
        int c = 18 * role + 2 * i;
        hrow[c]     = h0;
        hrow[c + 1] = h1;
    }
    __syncwarp();

    // ---- GEMM2: role owns output pairs [p0, p0+np) ----
    const int p0 = (role < 2) ? role * 5 : 10 + (role - 2) * 4;
    const int np = (role < 2) ? 5 : 4;

    ull acc2[5];
#pragma unroll
    for (int q = 0; q < 5; q++) acc2[q] = (q < np) ? b2p[p0 + q] : 0ull;

#pragma unroll 2
    for (int k = 0; k < 70; k++) {
        float hv = hrow[k];
        ull xx = pack2(hv, hv);
        const ull* wr = w2p + k * 18 + p0;
#pragma unroll
        for (int q = 0; q < 5; q++)
            if (q < np) FMA2(acc2[q], wr[q], xx, acc2[q]);
    }

    if (valid) {
        float* orow = out + node * EMB;
#pragma unroll
        for (int q = 0; q < 5; q++) {
            if (q < np) {
                float v0, v1;
                unpack2(acc2[q], v0, v1);
                int c = 2 * (p0 + q);
                orow[c] = v0;
                if (c + 1 < EMB) orow[c + 1] = v1;
            }
        }
    }
}

// =====================================================================
// launch
// =====================================================================
extern "C" void kernel_launch(void* const* d_in, const int* in_sizes, int n_in,
                              void* d_out, int out_size) {
    const float* fa = (const float*)d_in[0];
    const float* fb = (const float*)d_in[1];

    TArgs t;
    const float* fsrc[4] = { fb, fb, fa, fa };
    const float* fdst[4] = { fa, fa, fb, fb };
    for (int j = 0; j < 4; j++) {
        t.fsrc[j] = fsrc[j];
        t.fdst[j] = fdst[j];
        t.W[j]   = (const float*)d_in[6 + 3 * j];
        t.b[j]   = (const float*)d_in[7 + 3 * j];
        t.att[j] = (const float*)d_in[8 + 3 * j];
    }
    AArgs a;
    a.dst[0] = (const int*)d_in[2];
    a.dst[1] = (const int*)d_in[3];
    a.dst[2] = (const int*)d_in[4];
    a.dst[3] = (const int*)d_in[5];

    const float* W1 = (const float*)d_in[18];
    const float* b1 = (const float*)d_in[19];
    const float* al = (const float*)d_in[20];
    const float* W2 = (const float*)d_in[21];
    const float* b2 = (const float*)d_in[22];
    float* out = (float*)d_out;

    dim3 tg((NNODE + 127) / 128, 2);
    transform_kernel<<<tg, 128>>>(t);

    dim3 ag((NNODE + 7) / 8, 4);
    agg_kernel<<<ag, 256>>>(a);

    dim3 ug((2 * NNODE + 63) / 64);
    update_kernel<<<ug, 256>>>(fa, fb, W1, b1, al, W2, b2, out);
}

// round 6
// speedup vs baseline: 1.1868x; 1.0574x over previous
#include <cuda_runtime.h>
#include <cuda_fp16.h>
#include <math.h>

#define NNODE 50000
#define EMB 35
#define DEG 32
#define NBH 36          // halves per nb row (35 ch + 1 zero pad) = 72B = 9 ull
#define MSTR 36         // g_m row stride (floats) -> 16B-aligned float4 writes

typedef unsigned long long ull;

// ---------------- scratch (device globals; no runtime allocation) ----------------
__device__ __half g_nbh[4][NNODE * NBH];   // transformed neighbor rows, fp16, 72B/row
__device__ float  g_sb[4][NNODE];          // dst-side attention score (fp32, compact)
__device__ float  g_sa[4][NNODE];          // src-side attention score
__device__ float  g_m [4][NNODE * MSTR];   // aggregation results (padded rows)

// ---------------- packed f32x2 helpers ----------------
static __device__ __forceinline__ ull pack2(float a, float b) {
    ull r;
    unsigned int lo = __float_as_uint(a), hi = __float_as_uint(b);
    asm("mov.b64 %0, {%1, %2};" : "=l"(r) : "r"(lo), "r"(hi));
    return r;
}
static __device__ __forceinline__ void unpack2(ull v, float &a, float &b) {
    unsigned int lo, hi;
    asm("mov.b64 {%0, %1}, %2;" : "=r"(lo), "=r"(hi) : "l"(v));
    a = __uint_as_float(lo);
    b = __uint_as_float(hi);
}
#define FMA2(d, a, b, c) \
    asm("fma.rn.f32x2 %0, %1, %2, %3;" : "=l"(d) : "l"(a), "l"(b), "l"(c))

// ---------------- kernel args ----------------
struct TArgs {
    const float* fsrc[4];
    const float* fdst[4];
    const float* W[4];
    const float* b[4];
    const float* att[4];
};
struct AArgs {
    const int* dst[4];
};

// =====================================================================
// Kernel 1: nb = fsrc @ W + b (fp16 out); s_b = nb.att_hi; s_a = fdst.att_lo
// 2 threads per row (half = 18 channels each) -> ~40 regs, high occupancy.
// jobs on gridDim.y. 256 threads = 128 rows per block.
// =====================================================================
__global__ __launch_bounds__(256) void transform_kernel(TArgs args) {
    const int jid = blockIdx.y;
    const float* __restrict__ W   = args.W[jid];
    const float* __restrict__ bv  = args.b[jid];
    const float* __restrict__ att = args.att[jid];

    __shared__ __align__(16) float Wsh[EMB * 36];   // 5040B, rows padded to 36
    __shared__ __align__(16) ull bp[18];
    __shared__ __align__(16) ull ahp[18];
    __shared__ __align__(16) float alo[36];

    const int tid = threadIdx.x;
    for (int i = tid; i < EMB * 36; i += 256) {
        int k = i / 36, c = i % 36;
        Wsh[i] = (c < EMB) ? W[k * EMB + c] : 0.0f;
    }
    if (tid < 18) {
        int c = 2 * tid;
        bp[tid]  = pack2(bv[c],        (c + 1 < EMB) ? bv[c + 1]        : 0.0f);
        ahp[tid] = pack2(att[EMB + c], (c + 1 < EMB) ? att[EMB + c + 1] : 0.0f);
    }
    if (tid < 36) alo[tid] = (tid < EMB) ? att[tid] : 0.0f;
    __syncthreads();

    const int row_l = tid >> 1;
    const int half  = tid & 1;
    int row = blockIdx.x * 128 + row_l;
    const bool valid = (row < NNODE);
    if (!valid) row = NNODE - 1;          // keep warp converged for shfl

    // ---- GEMM half-row: channels [18*half, 18*half+18) ----
    ull acc[9];
#pragma unroll
    for (int i = 0; i < 9; i++) acc[i] = bp[9 * half + i];

    const float* xr = args.fsrc[jid] + row * EMB;
#pragma unroll 5
    for (int k = 0; k < EMB; k++) {
        float xv = __ldg(xr + k);
        ull xx = pack2(xv, xv);
        const ull* wr = reinterpret_cast<const ull*>(Wsh) + k * 18 + 9 * half;
#pragma unroll
        for (int i = 0; i < 9; i++) FMA2(acc[i], wr[i], xx, acc[i]);
    }

    // ---- s_b: partial dot with att_hi, combine halves via shfl ----
    {
        ull sp = 0ull;
#pragma unroll
        for (int i = 0; i < 9; i++) FMA2(sp, acc[i], ahp[9 * half + i], sp);
        float x0, y0;
        unpack2(sp, x0, y0);
        float ps = x0 + y0;
        ps += __shfl_xor_sync(0xffffffffu, ps, 1);
        if (valid && half == 0) g_sb[jid][row] = ps;
    }

    // ---- fp16 store: this half owns 9 uint (half2) ----
    if (valid) {
        unsigned int* r =
            reinterpret_cast<unsigned int*>(&g_nbh[jid][row * NBH]) + 9 * half;
#pragma unroll
        for (int i = 0; i < 9; i++) {
            float f0, f1;
            unpack2(acc[i], f0, f1);
            __half2 h = __floats2half2_rn(f0, f1);
            r[i] = *reinterpret_cast<unsigned int*>(&h);
        }
    }

    // ---- s_a: split k range between halves, combine via shfl ----
    {
        const float* yr = args.fdst[jid] + row * EMB;
        float sa = 0.0f;
        int k0 = half ? 18 : 0;
        int k1 = half ? EMB : 18;
        for (int k = k0; k < k1; k++) sa = fmaf(__ldg(yr + k), alo[k], sa);
        sa += __shfl_xor_sync(0xffffffffu, sa, 1);
        if (valid && half == 0) g_sa[jid][row] = sa;
    }
}

// =====================================================================
// Kernel 2: attention aggregation. One warp per node.
// Row = 9 x 8B. lane = sub*9 + piece: 3 edges gathered per warp LDG.64.
// Lanes 27-31 duplicate sub=2 loads (coalesce-dedup, no extra sectors).
// 33 edge slots (slot 32 weight 0), 11 iterations.
// =====================================================================
__global__ __launch_bounds__(256) void agg_kernel(AArgs args) {
    const int jid = blockIdx.y;
    const ull* __restrict__ nb = reinterpret_cast<const ull*>(g_nbh[jid]);
    const float* __restrict__ sbv = g_sb[jid];
    const float* __restrict__ sav = g_sa[jid];
    const int*   __restrict__ dst = args.dst[jid];
    float* __restrict__ m = g_m[jid];

    __shared__ float sw[8][36];
    __shared__ int   soff[8][36];

    const int wid  = threadIdx.x >> 5;
    const int lane = threadIdx.x & 31;
    const int node = blockIdx.x * 8 + wid;
    if (node >= NNODE) return;

    // ---- phase 1: per-edge weights (all 32 lanes) ----
    const int d = dst[node * DEG + lane];
    float x = sav[node] + sbv[d];
    float e = (x > 0.0f) ? x : 0.1f * expm1f(x);   // elu(alpha=0.1)
    float w = expf(e);

    float wsum = w;
#pragma unroll
    for (int o = 16; o; o >>= 1) wsum += __shfl_xor_sync(0xffffffffu, wsum, o);

    sw[wid][lane]   = w;
    soff[wid][lane] = d * 9;               // ull index of row start
    if (lane == 0) { sw[wid][32] = 0.0f; soff[wid][32] = 0; }
    __syncwarp();

    // ---- phase 2: 3 edges per iteration ----
    const int sub   = (lane < 27) ? (lane / 9) : 2;
    const int piece = (lane < 27) ? (lane % 9) : (lane - 27);

    float a0 = 0.0f, a1 = 0.0f, a2 = 0.0f, a3 = 0.0f;
#pragma unroll
    for (int it = 0; it < 11; it++) {
        int j = it * 3 + sub;
        float wj = sw[wid][j];
        ull v = nb[soff[wid][j] + piece];   // LDG.64: 4 fp16 channels
        unsigned int lo, hi;
        asm("mov.b64 {%0, %1}, %2;" : "=r"(lo), "=r"(hi) : "l"(v));
        float2 f0 = __half22float2(*reinterpret_cast<__half2*>(&lo));
        float2 f1 = __half22float2(*reinterpret_cast<__half2*>(&hi));
        a0 = fmaf(wj, f0.x, a0);
        a1 = fmaf(wj, f0.y, a1);
        a2 = fmaf(wj, f1.x, a2);
        a3 = fmaf(wj, f1.y, a3);
    }

    // ---- reduce sub groups (lanes p, p+9, p+18) ----
    {
        float t, u;
        t = __shfl_down_sync(0xffffffffu, a0, 9);
        u = __shfl_down_sync(0xffffffffu, a0, 18);
        a0 += t + u;
        t = __shfl_down_sync(0xffffffffu, a1, 9);
        u = __shfl_down_sync(0xffffffffu, a1, 18);
        a1 += t + u;
        t = __shfl_down_sync(0xffffffffu, a2, 9);
        u = __shfl_down_sync(0xffffffffu, a2, 18);
        a2 += t + u;
        t = __shfl_down_sync(0xffffffffu, a3, 9);
        u = __shfl_down_sync(0xffffffffu, a3, 18);
        a3 += t + u;
    }

    if (lane < 9) {
        float inv = 1.0f / wsum;
        float4 o = make_float4(a0 * inv, a1 * inv, a2 * inv, a3 * inv);
        *reinterpret_cast<float4*>(m + node * MSTR + 4 * lane) = o;
    }
}

// =====================================================================
// Kernel 3 (merged a+b): out = prelu([feat, m_pos, m_neg] @ W1 + b1) @ W2 + b2
// 4 threads per node, h exchanged via smem (quad in one warp).
// =====================================================================
__global__ __launch_bounds__(256, 3) void update_kernel(
    const float* __restrict__ fa, const float* __restrict__ fb,
    const float* __restrict__ W1, const float* __restrict__ b1,
    const float* __restrict__ alpha_p,
    const float* __restrict__ W2, const float* __restrict__ b2,
    float* __restrict__ out)
{
    __shared__ __align__(16) float W1sh[105 * 72];   // 30240B
    __shared__ __align__(16) ull   w2p[70 * 18];     // 10080B
    __shared__ __align__(16) float hs[64 * 73];      // 18688B
    __shared__ __align__(16) ull b1p[36];
    __shared__ __align__(16) ull b2p[18];

    const int tid = threadIdx.x;
    for (int i = tid; i < 105 * 72; i += 256) {
        int k = i / 72, c = i % 72;
        W1sh[i] = (c < 70) ? W1[k * 70 + c] : 0.0f;
    }
    for (int i = tid; i < 70 * 18; i += 256) {
        int k = i / 18, j = i % 18;
        int c = 2 * j;
        w2p[i] = pack2(W2[k * EMB + c], (c + 1 < EMB) ? W2[k * EMB + c + 1] : 0.0f);
    }
    if (tid < 36) {
        int c = 2 * tid;
        b1p[tid] = pack2(b1[c], (c + 1 < 70) ? b1[c + 1] : 0.0f);
    }
    if (tid < 18) {
        int c = 2 * tid;
        b2p[tid] = pack2(b2[c], (c + 1 < EMB) ? b2[c + 1] : 0.0f);
    }
    __syncthreads();

    const int node_l = tid >> 2;
    const int role   = tid & 3;
    const int node   = blockIdx.x * 64 + node_l;           // 0 .. 2*NNODE-1
    const bool valid = (node < 2 * NNODE);
    const int  nc    = valid ? node : (2 * NNODE - 1);

    const float* xr;
    const float* m0;
    const float* m1;
    if (nc < NNODE) {
        xr = fa + nc * EMB;
        m0 = g_m[0] + nc * MSTR;
        m1 = g_m[1] + nc * MSTR;
    } else {
        int nl = nc - NNODE;
        xr = fb + nl * EMB;
        m0 = g_m[2] + nl * MSTR;
        m1 = g_m[3] + nl * MSTR;
    }
    const float alpha = __ldg(alpha_p);

    // ---- GEMM1: this role computes h pairs [9*role, 9*role+9) ----
    ull acc[9];
#pragma unroll
    for (int i = 0; i < 9; i++) acc[i] = b1p[9 * role + i];

    const float* srcs[3] = { xr, m0, m1 };
    const ull* w1base = reinterpret_cast<const ull*>(W1sh) + 9 * role;
#pragma unroll
    for (int part = 0; part < 3; part++) {
        const float* x = srcs[part];
        const ull* wb = w1base + (part * EMB) * 36;
#pragma unroll 5
        for (int k = 0; k < EMB; k++) {
            float xv = x[k];
            ull xx = pack2(xv, xv);
            const ull* wr = wb + k * 36;
#pragma unroll
            for (int i = 0; i < 9; i++) FMA2(acc[i], wr[i], xx, acc[i]);
        }
    }

    // ---- PReLU, publish h to smem (quad lives in one warp) ----
    float* hrow = hs + node_l * 73;
#pragma unroll
    for (int i = 0; i < 9; i++) {
        float h0, h1;
        unpack2(acc[i], h0, h1);
        h0 = (h0 > 0.0f) ? h0 : alpha * h0;
        h1 = (h1 > 0.0f) ? h1 : alpha * h1;
        int c = 18 * role + 2 * i;
        hrow[c]     = h0;
        hrow[c + 1] = h1;
    }
    __syncwarp();

    // ---- GEMM2: role owns output pairs [p0, p0+np) ----
    const int p0 = (role < 2) ? role * 5 : 10 + (role - 2) * 4;
    const int np = (role < 2) ? 5 : 4;

    ull acc2[5];
#pragma unroll
    for (int q = 0; q < 5; q++) acc2[q] = (q < np) ? b2p[p0 + q] : 0ull;

#pragma unroll 2
    for (int k = 0; k < 70; k++) {
        float hv = hrow[k];
        ull xx = pack2(hv, hv);
        const ull* wr = w2p + k * 18 + p0;
#pragma unroll
        for (int q = 0; q < 5; q++)
            if (q < np) FMA2(acc2[q], wr[q], xx, acc2[q]);
    }

    if (valid) {
        float* orow = out + node * EMB;
#pragma unroll
        for (int q = 0; q < 5; q++) {
            if (q < np) {
                float v0, v1;
                unpack2(acc2[q], v0, v1);
                int c = 2 * (p0 + q);
                orow[c] = v0;
                if (c + 1 < EMB) orow[c + 1] = v1;
            }
        }
    }
}

// =====================================================================
// launch
// =====================================================================
extern "C" void kernel_launch(void* const* d_in, const int* in_sizes, int n_in,
                              void* d_out, int out_size) {
    const float* fa = (const float*)d_in[0];
    const float* fb = (const float*)d_in[1];

    TArgs t;
    const float* fsrc[4] = { fb, fb, fa, fa };
    const float* fdst[4] = { fa, fa, fb, fb };
    for (int j = 0; j < 4; j++) {
        t.fsrc[j] = fsrc[j];
        t.fdst[j] = fdst[j];
        t.W[j]   = (const float*)d_in[6 + 3 * j];
        t.b[j]   = (const float*)d_in[7 + 3 * j];
        t.att[j] = (const float*)d_in[8 + 3 * j];
    }
    AArgs a;
    a.dst[0] = (const int*)d_in[2];
    a.dst[1] = (const int*)d_in[3];
    a.dst[2] = (const int*)d_in[4];
    a.dst[3] = (const int*)d_in[5];

    const float* W1 = (const float*)d_in[18];
    const float* b1 = (const float*)d_in[19];
    const float* al = (const float*)d_in[20];
    const float* W2 = (const float*)d_in[21];
    const float* b2 = (const float*)d_in[22];
    float* out = (float*)d_out;

    dim3 tg((NNODE + 127) / 128, 4);
    transform_kernel<<<tg, 256>>>(t);

    dim3 ag((NNODE + 7) / 8, 4);
    agg_kernel<<<ag, 256>>>(a);

    dim3 ug((2 * NNODE + 63) / 64);
    update_kernel<<<ug, 256>>>(fa, fb, W1, b1, al, W2, b2, out);
}